// round 1
// baseline (speedup 1.0000x reference)
#include <cuda_runtime.h>
#include <math.h>

#define Tdim 1653
#define Ddim 512
#define Bdim 2
#define Edim 8
#define DE 64
#define BE 16
#define BT (Bdim * Tdim)                  // 3306
#define TDE (Tdim * DE)                   // 105792
static const long long TT = (long long)Tdim * Tdim;   // 2732409

// ------------------- scratch (static device allocations) -------------------
__device__ float g_Yq[BT * Ddim];
__device__ float g_Yk[BT * Ddim];
__device__ float g_Yv[BT * Ddim];
__device__ float g_Q [BE * TDE];
__device__ float g_K [BE * TDE];
__device__ float g_Vt[BE * TDE];          // per-head V transposed: [DE, T]
__device__ float g_S [(long long)BE * Tdim * Tdim];  // (Q K^T) * scale * punish
__device__ float g_A [(long long)BE * Tdim * Tdim];  // after orth GEMM + maskfill
__device__ float g_O [BE * TDE];          // attention output [T, DE] per head
__device__ float g_X [BT * Ddim];         // reassembled [B,T,D]

// ------------------- generic NT SGEMM: C[M,N] = A[M,K] * B[N,K]^T ----------
// MODE 0: plain   MODE 1: +bias[n]   MODE 2: *scale*punish[m*T+n]   MODE 3: maskfill(==0 -> -2e20)
template <int MODE>
__global__ void __launch_bounds__(256, 2)
sgemm_nt(const float* __restrict__ A, const float* __restrict__ B,
         float* __restrict__ C, int M, int N, int K,
         long long sA, long long sB, long long sC,
         const float* __restrict__ ep, float scale)
{
    const int bz = blockIdx.z;
    A += (long long)bz * sA;
    B += (long long)bz * sB;
    C += (long long)bz * sC;

    __shared__ __align__(16) float As[8][132];
    __shared__ __align__(16) float Bs[8][132];

    const int m0 = blockIdx.y * 128;
    const int n0 = blockIdx.x * 128;
    const int tid = threadIdx.x;
    const int tx = tid & 15;      // col group
    const int ty = tid >> 4;      // row group

    float acc[8][8];
#pragma unroll
    for (int i = 0; i < 8; ++i)
#pragma unroll
        for (int j = 0; j < 8; ++j) acc[i][j] = 0.f;

    const int row = tid >> 1;          // 0..127
    const int kb  = (tid & 1) * 4;     // 0 or 4
    const bool aOk = (m0 + row) < M;
    const bool bOk = (n0 + row) < N;
    const float* Aptr = A + (long long)(m0 + row) * K + kb;
    const float* Bptr = B + (long long)(n0 + row) * K + kb;

    const int kIters = (K + 7) / 8;
    for (int kt = 0; kt < kIters; ++kt) {
        const int k0 = kt * 8;
#pragma unroll
        for (int i = 0; i < 4; ++i) {
            const int kk = k0 + kb + i;
            As[kb + i][row] = (aOk && kk < K) ? Aptr[k0 + i] : 0.f;
            Bs[kb + i][row] = (bOk && kk < K) ? Bptr[k0 + i] : 0.f;
        }
        __syncthreads();
#pragma unroll
        for (int k = 0; k < 8; ++k) {
            float a[8], b[8];
            *(float4*)&a[0] = *(const float4*)&As[k][ty * 8];
            *(float4*)&a[4] = *(const float4*)&As[k][ty * 8 + 4];
            *(float4*)&b[0] = *(const float4*)&Bs[k][tx * 8];
            *(float4*)&b[4] = *(const float4*)&Bs[k][tx * 8 + 4];
#pragma unroll
            for (int i = 0; i < 8; ++i)
#pragma unroll
                for (int j = 0; j < 8; ++j)
                    acc[i][j] = fmaf(a[i], b[j], acc[i][j]);
        }
        __syncthreads();
    }

#pragma unroll
    for (int i = 0; i < 8; ++i) {
        const int m = m0 + ty * 8 + i;
        if (m >= M) continue;
#pragma unroll
        for (int j = 0; j < 8; ++j) {
            const int n = n0 + tx * 8 + j;
            if (n >= N) continue;
            float v = acc[i][j];
            if (MODE == 1) v += ep[n];
            if (MODE == 2) v = v * scale * ep[(long long)m * Tdim + n];
            if (MODE == 3) v = (v == 0.f) ? -2e20f : v;
            C[(long long)m * N + n] = v;
        }
    }
}

// ------------------- reshape / activation kernels --------------------------
// Forward split: Q[g].flat[f] = sigmoid(Y[b, f%T, e*64 + f/T]),  f = t2*64 + d2
__global__ void scatter_qkv_kernel()
{
    long long idx = (long long)blockIdx.x * 256 + threadIdx.x;
    const long long NTOT = (long long)BE * TDE;
    if (idx >= NTOT) return;
    const int g = (int)(idx / TDE);
    const int f = (int)(idx % TDE);
    const int b = g >> 3, e = g & 7;
    const int tt = f % Tdim;
    const int j  = f / Tdim;
    const long long src = ((long long)(b * Tdim + tt)) * Ddim + e * DE + j;

    const float yq = g_Yq[src];
    const float yk = g_Yk[src];
    g_Q[idx] = 1.2f / (1.f + expf(-1.6f * yq));
    g_K[idx] = 1.2f / (1.f + expf(-1.6f * yk));

    // V transposed per head: Vt[d2*T + t2] = V_logical[t2, d2]
    const int t2 = f / DE, d2 = f % DE;
    g_Vt[(long long)g * TDE + (long long)d2 * Tdim + t2] = g_Yv[src];
}

// Inverse reshape (clean): X[b, t, e*64+d2] = O[g=b*8+e][t, d2]
__global__ void gather_x_kernel()
{
    const int idx = blockIdx.x * 256 + threadIdx.x;
    if (idx >= BT * Ddim) return;
    const int b   = idx / (Tdim * Ddim);
    const int rem = idx % (Tdim * Ddim);
    const int t = rem / Ddim, d = rem % Ddim;
    const int g = b * Edim + (d >> 6);
    g_X[idx] = g_O[((long long)g * Tdim + t) * DE + (d & 63)];
}

// ------------------- launch ------------------------------------------------
extern "C" void kernel_launch(void* const* d_in, const int* in_sizes, int n_in,
                              void* d_out, int out_size)
{
    const float* input  = (const float*)d_in[0];
    const float* Wq     = (const float*)d_in[1];
    const float* bq     = (const float*)d_in[2];
    const float* Wk     = (const float*)d_in[3];
    const float* bk     = (const float*)d_in[4];
    const float* Wv     = (const float*)d_in[5];
    const float* bv     = (const float*)d_in[6];
    const float* Wo     = (const float*)d_in[7];
    const float* bo     = (const float*)d_in[8];
    const float* punish = (const float*)d_in[9];
    const float* orth   = (const float*)d_in[10];
    float* out = (float*)d_out;

    float *Yq, *Yk, *Yv, *Q, *Kb, *Vt, *S, *Aa, *O, *X;
    cudaGetSymbolAddress((void**)&Yq, g_Yq);
    cudaGetSymbolAddress((void**)&Yk, g_Yk);
    cudaGetSymbolAddress((void**)&Yv, g_Yv);
    cudaGetSymbolAddress((void**)&Q,  g_Q);
    cudaGetSymbolAddress((void**)&Kb, g_K);
    cudaGetSymbolAddress((void**)&Vt, g_Vt);
    cudaGetSymbolAddress((void**)&S,  g_S);
    cudaGetSymbolAddress((void**)&Aa, g_A);
    cudaGetSymbolAddress((void**)&O,  g_O);
    cudaGetSymbolAddress((void**)&X,  g_X);

    const float inv_sqrt_T = 1.0f / sqrtf((float)Tdim);
    const dim3 blk(256);

    // 1) projections: Y = x @ W^T + b   [3306,512] x [512,512]^T
    {
        dim3 grid((512 + 127) / 128, (BT + 127) / 128, 1);
        sgemm_nt<1><<<grid, blk>>>(input, Wq, Yq, BT, Ddim, Ddim, 0, 0, 0, bq, 0.f);
        sgemm_nt<1><<<grid, blk>>>(input, Wk, Yk, BT, Ddim, Ddim, 0, 0, 0, bk, 0.f);
        sgemm_nt<1><<<grid, blk>>>(input, Wv, Yv, BT, Ddim, Ddim, 0, 0, 0, bv, 0.f);
    }

    // 2) reshape + sigmoid + V transpose
    scatter_qkv_kernel<<<(BE * TDE + 255) / 256, blk>>>();

    // 3) S = (Q K^T) * (1/sqrt(T)) * punish    batched [1653,64]x[1653,64]^T
    {
        dim3 grid((Tdim + 127) / 128, (Tdim + 127) / 128, BE);
        sgemm_nt<2><<<grid, blk>>>(Q, Kb, S, Tdim, Tdim, DE,
                                   (long long)TDE, (long long)TDE, TT,
                                   punish, inv_sqrt_T);
    }

    // 4) A = S @ orth^T, then maskfill(==0 -> -2e20)   batched [1653,1653]^2
    {
        dim3 grid((Tdim + 127) / 128, (Tdim + 127) / 128, BE);
        sgemm_nt<3><<<grid, blk>>>(S, orth, Aa, Tdim, Tdim, Tdim,
                                   TT, TT, TT, nullptr, 0.f);
    }

    // 5) O = A @ V  (as NT against V^T)   batched [1653,1653] x [64,1653]^T
    {
        dim3 grid(1, (Tdim + 127) / 128, BE);
        sgemm_nt<0><<<grid, blk>>>(Aa, Vt, O, Tdim, DE, Tdim,
                                   TT, (long long)TDE, (long long)TDE,
                                   nullptr, 0.f);
    }

    // 6) inverse reshape
    gather_x_kernel<<<(BT * Ddim + 255) / 256, blk>>>();

    // 7) final projection: out = X @ Wo^T + bo
    {
        dim3 grid((512 + 127) / 128, (BT + 127) / 128, 1);
        sgemm_nt<1><<<grid, blk>>>(X, Wo, out, BT, Ddim, Ddim, 0, 0, 0, bo, 0.f);
    }
}

// round 2
// speedup vs baseline: 3.8777x; 3.8777x over previous
#include <cuda_runtime.h>
#include <math.h>

#define Tdim 1653
#define Ddim 512
#define Bdim 2
#define Edim 8
#define DE 64
#define BE 16
#define BT (Bdim * Tdim)                  // 3306
#define TDE (Tdim * DE)                   // 105792
static const long long TT = (long long)Tdim * Tdim;   // 2732409

// ------------------- scratch (static device allocations) -------------------
__device__ float g_Yq[BT * Ddim];
__device__ float g_Yk[BT * Ddim];
__device__ float g_Yv[BT * Ddim];
__device__ float g_Q [BE * TDE];          // per-head [T, 64]
__device__ float g_K [BE * TDE];          // per-head [T, 64]
__device__ float g_V [BE * TDE];          // per-head [T, 64]
__device__ float g_Wt[BE * TDE];          // per-head W^T: [64, T],  W = orth^T @ V
__device__ float g_S [(long long)BE * Tdim * Tdim];  // (Q K^T) * scale * punish
__device__ float g_O [BE * TDE];          // attention output [T, 64] per head
__device__ float g_X [BT * Ddim];         // reassembled [B,T,D]

// ------------------- generic NT SGEMM: C[M,N] = A[M,K] * B[N,K]^T ----------
// BM=128 fixed, 256 threads, micro tile 8 x TN.  BN/TN must equal 16.
// MODE 0: plain   MODE 1: +bias[n]   MODE 2: *scale*punish[m*T+n]
template <int BN, int TN, int MODE>
__global__ void __launch_bounds__(256, 2)
sgemm_nt(const float* __restrict__ A, const float* __restrict__ B,
         float* __restrict__ C, int M, int N, int K,
         long long sA, long long sB, long long sC,
         const float* __restrict__ ep, float scale)
{
    const int bz = blockIdx.z;
    A += (long long)bz * sA;
    B += (long long)bz * sB;
    C += (long long)bz * sC;

    __shared__ __align__(16) float As[8][128 + 4];
    __shared__ __align__(16) float Bs[8][BN + 4];

    const int m0 = blockIdx.y * 128;
    const int n0 = blockIdx.x * BN;
    const int tid = threadIdx.x;
    const int NG = BN / TN;          // 16
    const int tx = tid % NG;
    const int ty = tid / NG;         // 0..15

    float acc[8][TN];
#pragma unroll
    for (int i = 0; i < 8; ++i)
#pragma unroll
        for (int j = 0; j < TN; ++j) acc[i][j] = 0.f;

    const int kIters = (K + 7) / 8;
    for (int kt = 0; kt < kIters; ++kt) {
        const int k0 = kt * 8;
        // load A tile 128x8
#pragma unroll
        for (int i = tid; i < 128 * 8; i += 256) {
            const int m = i >> 3, kk = i & 7;
            As[kk][m] = (m0 + m < M && k0 + kk < K)
                        ? A[(long long)(m0 + m) * K + k0 + kk] : 0.f;
        }
        // load B tile BNx8
#pragma unroll
        for (int i = tid; i < BN * 8; i += 256) {
            const int n = i >> 3, kk = i & 7;
            Bs[kk][n] = (n0 + n < N && k0 + kk < K)
                        ? B[(long long)(n0 + n) * K + k0 + kk] : 0.f;
        }
        __syncthreads();
#pragma unroll
        for (int k = 0; k < 8; ++k) {
            float a[8], b[TN];
#pragma unroll
            for (int i = 0; i < 8; ++i)  a[i] = As[k][ty * 8 + i];
#pragma unroll
            for (int j = 0; j < TN; ++j) b[j] = Bs[k][tx * TN + j];
#pragma unroll
            for (int i = 0; i < 8; ++i)
#pragma unroll
                for (int j = 0; j < TN; ++j)
                    acc[i][j] = fmaf(a[i], b[j], acc[i][j]);
        }
        __syncthreads();
    }

#pragma unroll
    for (int i = 0; i < 8; ++i) {
        const int m = m0 + ty * 8 + i;
        if (m >= M) continue;
#pragma unroll
        for (int j = 0; j < TN; ++j) {
            const int n = n0 + tx * TN + j;
            if (n >= N) continue;
            float v = acc[i][j];
            if (MODE == 1) v += ep[n];
            if (MODE == 2) v = v * scale * ep[(long long)m * Tdim + n];
            C[(long long)m * N + n] = v;
        }
    }
}

// ------------- W^T kernel:  Wt[d, t] = sum_s orth[s, t] * V[s, d] ----------
// per head. grid: (ceil(T/128), BE), 256 threads, micro 4(d) x 8(t)
__global__ void __launch_bounds__(256, 2) wt_kernel(const float* __restrict__ orth)
{
    const int g = blockIdx.y;
    const float* V  = g_V  + (long long)g * TDE;      // [T, 64]
    const float* Og = orth + (long long)g * TT;       // [T, T]
    float* Wt = g_Wt + (long long)g * TDE;            // [64, T]

    __shared__ __align__(16) float Vs[8][64 + 4];
    __shared__ __align__(16) float Os[8][128 + 4];

    const int n0 = blockIdx.x * 128;                  // t range
    const int tid = threadIdx.x;
    const int tx = tid & 15;                          // t group (x8)
    const int ty = tid >> 4;                          // d group (x4)

    float acc[4][8];
#pragma unroll
    for (int i = 0; i < 4; ++i)
#pragma unroll
        for (int j = 0; j < 8; ++j) acc[i][j] = 0.f;

    const int kIters = (Tdim + 7) / 8;
    for (int kt = 0; kt < kIters; ++kt) {
        const int s0 = kt * 8;
#pragma unroll
        for (int i = tid; i < 8 * 64; i += 256) {
            const int kk = i >> 6, d = i & 63;
            Vs[kk][d] = (s0 + kk < Tdim) ? V[(long long)(s0 + kk) * DE + d] : 0.f;
        }
#pragma unroll
        for (int i = tid; i < 8 * 128; i += 256) {
            const int kk = i >> 7, t = i & 127;
            Os[kk][t] = (s0 + kk < Tdim && n0 + t < Tdim)
                        ? Og[(long long)(s0 + kk) * Tdim + n0 + t] : 0.f;
        }
        __syncthreads();
#pragma unroll
        for (int k = 0; k < 8; ++k) {
            float a[4], b[8];
#pragma unroll
            for (int i = 0; i < 4; ++i) a[i] = Vs[k][ty * 4 + i];
#pragma unroll
            for (int j = 0; j < 8; ++j) b[j] = Os[k][tx * 8 + j];
#pragma unroll
            for (int i = 0; i < 4; ++i)
#pragma unroll
                for (int j = 0; j < 8; ++j)
                    acc[i][j] = fmaf(a[i], b[j], acc[i][j]);
        }
        __syncthreads();
    }

#pragma unroll
    for (int i = 0; i < 4; ++i) {
        const int d = ty * 4 + i;
#pragma unroll
        for (int j = 0; j < 8; ++j) {
            const int t = n0 + tx * 8 + j;
            if (t < Tdim) Wt[(long long)d * Tdim + t] = acc[i][j];
        }
    }
}

// ------------------- reshape / activation kernels --------------------------
__global__ void scatter_qkv_kernel()
{
    long long idx = (long long)blockIdx.x * 256 + threadIdx.x;
    const long long NTOT = (long long)BE * TDE;
    if (idx >= NTOT) return;
    const int g = (int)(idx / TDE);
    const int f = (int)(idx % TDE);
    const int b = g >> 3, e = g & 7;
    const int tt = f % Tdim;
    const int j  = f / Tdim;
    const long long src = ((long long)(b * Tdim + tt)) * Ddim + e * DE + j;

    g_Q[idx] = 1.2f / (1.f + expf(-1.6f * g_Yq[src]));
    g_K[idx] = 1.2f / (1.f + expf(-1.6f * g_Yk[src]));
    g_V[idx] = g_Yv[src];
}

__global__ void gather_x_kernel()
{
    const int idx = blockIdx.x * 256 + threadIdx.x;
    if (idx >= BT * Ddim) return;
    const int b   = idx / (Tdim * Ddim);
    const int rem = idx % (Tdim * Ddim);
    const int t = rem / Ddim, d = rem % Ddim;
    const int g = b * Edim + (d >> 6);
    g_X[idx] = g_O[((long long)g * Tdim + t) * DE + (d & 63)];
}

// ------------------- launch ------------------------------------------------
extern "C" void kernel_launch(void* const* d_in, const int* in_sizes, int n_in,
                              void* d_out, int out_size)
{
    const float* input  = (const float*)d_in[0];
    const float* Wq     = (const float*)d_in[1];
    const float* bq     = (const float*)d_in[2];
    const float* Wk     = (const float*)d_in[3];
    const float* bk     = (const float*)d_in[4];
    const float* Wv     = (const float*)d_in[5];
    const float* bv     = (const float*)d_in[6];
    const float* Wo     = (const float*)d_in[7];
    const float* bo     = (const float*)d_in[8];
    const float* punish = (const float*)d_in[9];
    const float* orth   = (const float*)d_in[10];
    float* out = (float*)d_out;

    float *Yq, *Yk, *Yv, *Q, *Kb, *S, *Wt, *O;
    cudaGetSymbolAddress((void**)&Yq, g_Yq);
    cudaGetSymbolAddress((void**)&Yk, g_Yk);
    cudaGetSymbolAddress((void**)&Yv, g_Yv);
    cudaGetSymbolAddress((void**)&Q,  g_Q);
    cudaGetSymbolAddress((void**)&Kb, g_K);
    cudaGetSymbolAddress((void**)&S,  g_S);
    cudaGetSymbolAddress((void**)&Wt, g_Wt);
    cudaGetSymbolAddress((void**)&O,  g_O);
    float* X;
    cudaGetSymbolAddress((void**)&X, g_X);

    const float inv_sqrt_T = 1.0f / sqrtf((float)Tdim);
    const dim3 blk(256);

    // 1) projections: Y = x @ W^T + b   [3306,512] x [512,512]^T
    {
        dim3 grid(512 / 128, (BT + 127) / 128, 1);
        sgemm_nt<128, 8, 1><<<grid, blk>>>(input, Wq, Yq, BT, Ddim, Ddim, 0, 0, 0, bq, 0.f);
        sgemm_nt<128, 8, 1><<<grid, blk>>>(input, Wk, Yk, BT, Ddim, Ddim, 0, 0, 0, bk, 0.f);
        sgemm_nt<128, 8, 1><<<grid, blk>>>(input, Wv, Yv, BT, Ddim, Ddim, 0, 0, 0, bv, 0.f);
    }

    // 2) reshape + sigmoid
    scatter_qkv_kernel<<<(BE * TDE + 255) / 256, blk>>>();

    // 3) W^T = (orth^T @ V)^T  per head
    {
        dim3 grid((Tdim + 127) / 128, BE, 1);
        wt_kernel<<<grid, blk>>>(orth);
    }

    // 4) S = (Q K^T) * (1/sqrt(T)) * punish    batched [1653,64]x[1653,64]^T
    {
        dim3 grid((Tdim + 127) / 128, (Tdim + 127) / 128, BE);
        sgemm_nt<128, 8, 2><<<grid, blk>>>(Q, Kb, S, Tdim, Tdim, DE,
                                           (long long)TDE, (long long)TDE, TT,
                                           punish, inv_sqrt_T);
    }

    // 5) O = S @ W   == NT gemm against Wt[64, T]   batched [1653,1653]x[64,1653]^T
    {
        dim3 grid(1, (Tdim + 127) / 128, BE);
        sgemm_nt<64, 4, 0><<<grid, blk>>>(S, Wt, O, Tdim, DE, Tdim,
                                          TT, (long long)TDE, (long long)TDE,
                                          nullptr, 0.f);
    }

    // 6) inverse reshape
    gather_x_kernel<<<(BT * Ddim + 255) / 256, blk>>>();

    // 7) final projection: out = X @ Wo^T + bo
    {
        dim3 grid(512 / 128, (BT + 127) / 128, 1);
        sgemm_nt<128, 8, 1><<<grid, blk>>>(X, Wo, out, BT, Ddim, Ddim, 0, 0, 0, bo, 0.f);
    }
}